// round 1
// baseline (speedup 1.0000x reference)
#include <cuda_runtime.h>
#include <math.h>

// ---------------- problem constants ----------------
#define Hd   200
#define Bn   32
#define Ln   64
#define Mn   3
#define An   2048            // Bn*Ln nodes per modality
#define Nn   6144            // Mn*An total nodes
#define AH   (An*Hd)         // 409600
#define INV_PI 0.31830988618379067f

// ---------------- scratch (static device globals; no allocs) ----------------
__device__ float g_feats [Nn*Hd];
__device__ float g_nrm   [Nn*Hd];
__device__ float g_intra [Mn*Bn*Ln*Ln];   // 96 blocks of 64x64
__device__ float g_cdot  [3*An];          // pair dots (01,02,12), angular-transformed
__device__ float g_crossw[9*An];          // normalized cross weights [m][n][a]
__device__ float g_dinv  [Nn];
__device__ float g_h     [Nn*Hd];
__device__ float g_h0    [Nn*Hd];
__device__ float g_hi    [Nn*Hd];
__device__ float g_hx    [3*AH];
__device__ float g_z     [6*AH];
__device__ float g_out3  [3*AH];

__constant__ int c_jtab[6] = {1,2,0,2,0,1}; // partner modality per gate pair

__device__ __forceinline__ float ang_sim(float d) {
    d *= 0.99999f;
    d = fminf(fmaxf(d, -1.f), 1.f);
    return 1.f - acosf(d) * INV_PI;
}

// ---------------- K1: copy features + row-normalize ----------------
__global__ void prep_kernel(const float* __restrict__ xa,
                            const float* __restrict__ xv,
                            const float* __restrict__ xt) {
    int w = threadIdx.x >> 5, lane = threadIdx.x & 31;
    int u = blockIdx.x * 8 + w;           // < 6144
    int m = u >> 11, a = u & 2047;
    const float* src = (m == 0 ? xa : (m == 1 ? xv : xt)) + a * Hd;
    float vals[7]; float ss = 0.f;
#pragma unroll
    for (int i = 0; i < 7; i++) {
        int c = lane + i * 32;
        float v = (c < Hd) ? src[c] : 0.f;
        vals[i] = v; ss += v * v;
    }
#pragma unroll
    for (int o = 16; o; o >>= 1) ss += __shfl_xor_sync(0xffffffffu, ss, o);
    float rn = rsqrtf(ss);
#pragma unroll
    for (int i = 0; i < 7; i++) {
        int c = lane + i * 32;
        if (c < Hd) {
            g_feats[u * Hd + c] = vals[i];
            g_nrm  [u * Hd + c] = vals[i] * rn;
        }
    }
}

// ---------------- K2: intra-dialogue 64x64 gram blocks (angular sim) ----------------
__global__ void intra_kernel() {
    int mb = blockIdx.x;                  // 0..95
    const float* blk = g_nrm + mb * 64 * Hd;
    __shared__ float s[40][68];           // s[kk][row]
    int t = threadIdx.x;
    int tx = t & 15, ty = t >> 4;
    float acc[4][4] = {};
    for (int h0c = 0; h0c < Hd; h0c += 40) {
        __syncthreads();
#pragma unroll
        for (int k = 0; k < 10; k++) {
            int idx = t + k * 256;        // < 2560
            int r = idx / 40, c = idx % 40;
            s[c][r] = blk[r * Hd + h0c + c];
        }
        __syncthreads();
#pragma unroll 4
        for (int kk = 0; kk < 40; kk++) {
            float a[4], b[4];
#pragma unroll
            for (int ii = 0; ii < 4; ii++) a[ii] = s[kk][ty * 4 + ii];
#pragma unroll
            for (int jj = 0; jj < 4; jj++) b[jj] = s[kk][tx * 4 + jj];
#pragma unroll
            for (int ii = 0; ii < 4; ii++)
#pragma unroll
                for (int jj = 0; jj < 4; jj++)
                    acc[ii][jj] = fmaf(a[ii], b[jj], acc[ii][jj]);
        }
    }
#pragma unroll
    for (int ii = 0; ii < 4; ii++)
#pragma unroll
        for (int jj = 0; jj < 4; jj++)
            g_intra[mb * 4096 + (ty * 4 + ii) * 64 + (tx * 4 + jj)] = ang_sim(acc[ii][jj]);
}

// ---------------- K3: cross-modal per-utterance dots ----------------
__global__ void crossdot_kernel() {
    int w = threadIdx.x >> 5, lane = threadIdx.x & 31;
    int a = blockIdx.x * 8 + w;           // < 2048
    const float* p0 = g_nrm + (0 * An + a) * Hd;
    const float* p1 = g_nrm + (1 * An + a) * Hd;
    const float* p2 = g_nrm + (2 * An + a) * Hd;
    float s01 = 0.f, s02 = 0.f, s12 = 0.f;
    for (int c = lane; c < Hd; c += 32) {
        float v0 = p0[c], v1 = p1[c], v2 = p2[c];
        s01 = fmaf(v0, v1, s01); s02 = fmaf(v0, v2, s02); s12 = fmaf(v1, v2, s12);
    }
#pragma unroll
    for (int o = 16; o; o >>= 1) {
        s01 += __shfl_xor_sync(0xffffffffu, s01, o);
        s02 += __shfl_xor_sync(0xffffffffu, s02, o);
        s12 += __shfl_xor_sync(0xffffffffu, s12, o);
    }
    if (lane == 0) {
        g_cdot[0 * An + a] = ang_sim(s01);
        g_cdot[1 * An + a] = ang_sim(s02);
        g_cdot[2 * An + a] = ang_sim(s12);
    }
}

// ---------------- K4: degrees -> dinv ----------------
__global__ void degree_kernel() {
    int u = blockIdx.x * 256 + threadIdx.x;   // < 6144
    int m = u >> 11, a = u & 2047, l = u & 63;
    int mb = u >> 6;
    const float* row = g_intra + mb * 4096 + l * 64;
    float s = 0.f;
#pragma unroll 8
    for (int j = 0; j < 64; j++) s += row[j];
    float c0 = g_cdot[a], c1 = g_cdot[An + a], c2 = g_cdot[2 * An + a];
    s += (m == 0) ? (c0 + c1) : (m == 1) ? (c0 + c2) : (c1 + c2);
    g_dinv[u] = rsqrtf(s);
}

// ---------------- K5a: scale intra blocks ----------------
__global__ void scale_intra_kernel() {
    int idx = blockIdx.x * 256 + threadIdx.x;  // < 393216
    int mb = idx >> 12, i = (idx >> 6) & 63, j = idx & 63;
    g_intra[idx] *= g_dinv[mb * 64 + i] * g_dinv[mb * 64 + j];
}

// ---------------- K5b: scale cross weights ----------------
__global__ void scale_cross_kernel() {
    int idx = blockIdx.x * 256 + threadIdx.x;  // < 12288
    int pr = idx >> 11, a = idx & 2047;
    const int mt[6] = {0,0,1,1,2,2};
    const int nt[6] = {1,2,0,2,0,1};
    const int dt[6] = {0,1,0,2,1,2};
    int m = mt[pr], n = nt[pr];
    g_crossw[(m * 3 + n) * An + a] =
        g_cdot[dt[pr] * An + a] * g_dinv[m * An + a] * g_dinv[n * An + a];
}

// ---------------- K6: structured adj @ h  (g_h -> g_hi) ----------------
__global__ void adjmul_kernel() {
    int mb = blockIdx.x;                      // 0..95
    int m = mb >> 5, b = mb & 31;
    __shared__ float si[64][65];              // normalized intra block [i][j]
    __shared__ float hs[64][40];              // h chunk [j][cc]
    int t = threadIdx.x;
    int i = t & 63, cq = t >> 6;              // cq 0..3
#pragma unroll
    for (int k = 0; k < 16; k++) {
        int idx = t + k * 256;                // < 4096
        si[idx >> 6][idx & 63] = g_intra[mb * 4096 + idx];
    }
    int a = b * 64 + i;
    int n0 = (m == 0) ? 1 : 0;
    int n1 = (m == 2) ? 1 : 2;
    float w0 = g_crossw[(m * 3 + n0) * An + a];
    float w1 = g_crossw[(m * 3 + n1) * An + a];
    const float* h0r = g_h + (n0 * An + a) * Hd;
    const float* h1r = g_h + (n1 * An + a) * Hd;
    int rowbase = m * An + b * 64;
    for (int cc = 0; cc < Hd; cc += 40) {
        __syncthreads();
#pragma unroll
        for (int k = 0; k < 10; k++) {
            int idx = t + k * 256;            // < 2560
            int r = idx / 40, c = idx % 40;
            hs[r][c] = g_h[(rowbase + r) * Hd + cc + c];
        }
        __syncthreads();
        float acc[10] = {};
#pragma unroll 8
        for (int j = 0; j < 64; j++) {
            float aij = si[i][j];
#pragma unroll
            for (int q = 0; q < 10; q++)
                acc[q] = fmaf(aij, hs[j][cq * 10 + q], acc[q]);
        }
#pragma unroll
        for (int q = 0; q < 10; q++) {
            int c = cc + cq * 10 + q;
            g_hi[(rowbase + i) * Hd + c] = acc[q] + w0 * h0r[c] + w1 * h1r[c];
        }
    }
}

// ---------------- generic skinny GEMM: C[M,200] = epi(A[M,K] @ W[K,200]) --------
// MODE 0: fc0   (A=feats, K=200, relu+bias, writes g_h AND g_h0)
// MODE 1: conv  (A=[hi|h0], K=400, gcnii epilogue, writes g_h)
// MODE 2: tm    (A=[feats_m|h_m], K=400, relu+bias, z=modality, writes g_hx)
// MODE 3: cross (A=[hx_i|hx_j|hx_i*hx_j], K=600, sigmoid+bias, z=pair, writes g_z)
template<int MODE>
__global__ void gemm_k(const float* __restrict__ Wg,
                       const float* __restrict__ biasg, float beta) {
    constexpr int K = (MODE == 0) ? 200 : ((MODE == 3) ? 600 : 400);
    const int z = blockIdx.z;
    const float *A0, *A1 = nullptr;
    float *C, *C2 = nullptr;
    const float* bias = nullptr;
    if (MODE == 0)      { A0 = g_feats; C = g_h; C2 = g_h0; bias = biasg; }
    else if (MODE == 1) { A0 = g_hi; A1 = g_h0; C = g_h; }
    else if (MODE == 2) { A0 = g_feats + z * AH; A1 = g_h + z * AH;
                          C = g_hx + z * AH; bias = biasg + z * Hd; }
    else                { int ii = z >> 1; int jj = c_jtab[z];
                          A0 = g_hx + ii * AH; A1 = g_hx + jj * AH;
                          C = g_z + z * AH; bias = biasg + z * Hd; }
    const float* W = Wg + z * K * Hd;

    __shared__ float As[64][9];
    __shared__ float Bs[8][200];
    int t = threadIdx.x;
    int tx = t & 7, ty = t >> 3;              // ty 0..31; rows {2ty,2ty+1}, cols tx*25..
    int row0 = blockIdx.y * 64;
    float acc0[25] = {}, acc1[25] = {};

    for (int k0 = 0; k0 < K; k0 += 8) {
#pragma unroll
        for (int ld = 0; ld < 2; ld++) {
            int idx = t * 2 + ld;
            int r = idx >> 3, kk = idx & 7;
            int k = k0 + kk;
            int grow = row0 + r;
            float v;
            if (MODE == 3) {
                if (k < 200)      v = A0[grow * Hd + k];
                else if (k < 400) v = A1[grow * Hd + k - 200];
                else { int kr = k - 400; v = A0[grow * Hd + kr] * A1[grow * Hd + kr]; }
            } else if (K == 400) {
                v = (k < 200) ? A0[grow * Hd + k] : A1[grow * Hd + k - 200];
            } else {
                v = A0[grow * Hd + k];
            }
            As[r][kk] = v;
        }
        for (int idx = t; idx < 1600; idx += 256) {
            int kk = idx / 200, c = idx % 200;
            Bs[kk][c] = W[(k0 + kk) * Hd + c];
        }
        __syncthreads();
#pragma unroll
        for (int kk = 0; kk < 8; kk++) {
            float a0 = As[2 * ty][kk];
            float a1 = As[2 * ty + 1][kk];
#pragma unroll
            for (int q = 0; q < 25; q++) {
                float bv = Bs[kk][tx * 25 + q];
                acc0[q] = fmaf(a0, bv, acc0[q]);
                acc1[q] = fmaf(a1, bv, acc1[q]);
            }
        }
        __syncthreads();
    }

    int r0 = row0 + 2 * ty, r1 = r0 + 1;
    float omb = 1.f - beta;
#pragma unroll
    for (int q = 0; q < 25; q++) {
        int c = tx * 25 + q;
        float v0 = acc0[q], v1 = acc1[q];
        if (MODE == 0) {
            v0 = fmaxf(v0 + bias[c], 0.f); v1 = fmaxf(v1 + bias[c], 0.f);
            C[r0 * Hd + c] = v0; C2[r0 * Hd + c] = v0;
            C[r1 * Hd + c] = v1; C2[r1 * Hd + c] = v1;
        } else if (MODE == 1) {
            float e0 = 0.9f * g_hi[r0 * Hd + c] + 0.1f * g_h0[r0 * Hd + c];
            float e1 = 0.9f * g_hi[r1 * Hd + c] + 0.1f * g_h0[r1 * Hd + c];
            C[r0 * Hd + c] = fmaxf(beta * v0 + omb * e0, 0.f);
            C[r1 * Hd + c] = fmaxf(beta * v1 + omb * e1, 0.f);
        } else if (MODE == 2) {
            C[r0 * Hd + c] = fmaxf(v0 + bias[c], 0.f);
            C[r1 * Hd + c] = fmaxf(v1 + bias[c], 0.f);
        } else {
            C[r0 * Hd + c] = 1.f / (1.f + expf(-(v0 + bias[c])));
            C[r1 * Hd + c] = 1.f / (1.f + expf(-(v1 + bias[c])));
        }
    }
}

// ---------------- K7: gated combine ----------------
__global__ void combine_kernel() {
    int idx = blockIdx.x * 256 + threadIdx.x;     // < 3*AH
    int m = idx / AH, e = idx - m * AH;
    int p0 = 2 * m, p1 = 2 * m + 1;
    int j0 = c_jtab[p0], j1 = c_jtab[p1];
    float xi = g_hx[m * AH + e];
    float z0 = g_z[p0 * AH + e], z1 = g_z[p1 * AH + e];
    g_out3[idx] = z0 * xi + (1.f - z0) * g_hx[j0 * AH + e]
                + z1 * xi + (1.f - z1) * g_hx[j1 * AH + e];
}

// ---------------- K8: final logits (sum over modalities) ----------------
__global__ void joint_kernel(const float* __restrict__ uw,
                             const float* __restrict__ ub,
                             float* __restrict__ out) {
    __shared__ float su[3600];
    __shared__ float sb[6];
    int t = threadIdx.x;
    for (int i = t; i < 3600; i += 256) su[i] = uw[i];
    if (t < 6) sb[t] = ub[t] + ub[6 + t] + ub[12 + t];
    __syncthreads();
    int w = t >> 5, lane = t & 31;
    int a = blockIdx.x * 8 + w;                   // < 2048
    float acc[6] = {};
#pragma unroll
    for (int m = 0; m < 3; m++) {
        const float* orow = g_out3 + m * AH + a * Hd;
        const float* wm = su + m * 1200;
        for (int c = lane; c < Hd; c += 32) {
            float v = orow[c];
#pragma unroll
            for (int tg = 0; tg < 6; tg++)
                acc[tg] = fmaf(v, wm[c * 6 + tg], acc[tg]);
        }
    }
#pragma unroll
    for (int o = 16; o; o >>= 1)
#pragma unroll
        for (int tg = 0; tg < 6; tg++)
            acc[tg] += __shfl_xor_sync(0xffffffffu, acc[tg], o);
    if (lane == 0)
#pragma unroll
        for (int tg = 0; tg < 6; tg++)
            out[a * 6 + tg] = acc[tg] + sb[tg];
}

// ---------------- host launcher ----------------
extern "C" void kernel_launch(void* const* d_in, const int* in_sizes, int n_in,
                              void* d_out, int out_size) {
    const float* x_a     = (const float*)d_in[0];
    const float* x_v     = (const float*)d_in[1];
    const float* x_t     = (const float*)d_in[2];
    const float* fc0_w   = (const float*)d_in[3];
    const float* fc0_b   = (const float*)d_in[4];
    const float* conv_w  = (const float*)d_in[5];
    const float* tm_w    = (const float*)d_in[6];
    const float* tm_b    = (const float*)d_in[7];
    const float* cross_w = (const float*)d_in[8];
    const float* cross_b = (const float*)d_in[9];
    const float* uni_w   = (const float*)d_in[10];
    const float* uni_b   = (const float*)d_in[11];
    float* out = (float*)d_out;

    const float beta0 = 0.40546510810816438f;  // log(1.5)
    const float beta1 = 0.22314355131420976f;  // log(1.25)

    prep_kernel<<<768, 256>>>(x_a, x_v, x_t);
    intra_kernel<<<96, 256>>>();
    crossdot_kernel<<<256, 256>>>();
    degree_kernel<<<24, 256>>>();
    scale_intra_kernel<<<1536, 256>>>();
    scale_cross_kernel<<<48, 256>>>();

    gemm_k<0><<<dim3(1, 96, 1), 256>>>(fc0_w, fc0_b, 0.f);

    adjmul_kernel<<<96, 256>>>();
    gemm_k<1><<<dim3(1, 96, 1), 256>>>(conv_w, nullptr, beta0);
    adjmul_kernel<<<96, 256>>>();
    gemm_k<1><<<dim3(1, 96, 1), 256>>>(conv_w + 400 * Hd, nullptr, beta1);

    gemm_k<2><<<dim3(1, 32, 3), 256>>>(tm_w, tm_b, 0.f);
    gemm_k<3><<<dim3(1, 32, 6), 256>>>(cross_w, cross_b, 0.f);

    combine_kernel<<<4800, 256>>>();
    joint_kernel<<<256, 256>>>(uni_w, uni_b, out);
}

// round 2
// speedup vs baseline: 1.5860x; 1.5860x over previous
#include <cuda_runtime.h>
#include <math.h>

typedef unsigned long long u64;

// ---------------- problem constants ----------------
#define Hd   200
#define An   2048            // nodes per modality
#define Nn   6144            // total nodes
#define AH   (An*Hd)         // 409600
#define INV_PI 0.31830988618379067f

// ---------------- scratch (static device globals; no allocs) ----------------
__device__ float g_feats [Nn*Hd];
__device__ float g_nrm   [Nn*Hd];
__device__ float g_intra [96*4096];       // 96 blocks of 64x64 (raw angular sim)
__device__ float g_cdot  [3*An];          // pair dots (01,02,12), angular-transformed
__device__ float g_crossw[9*An];          // normalized cross weights [m][n][a]
__device__ float g_dinv  [Nn];
__device__ float g_h     [Nn*Hd];
__device__ float g_h0    [Nn*Hd];
__device__ float g_hi    [Nn*Hd];
__device__ float g_hx    [3*AH];
__device__ float g_z     [6*AH];

__constant__ int c_jtab[6] = {1,2,0,2,0,1}; // partner modality per gate pair

// ---------------- packed fp32 helpers ----------------
__device__ __forceinline__ u64 ffma2(u64 a, u64 b, u64 c) {
    u64 d; asm("fma.rn.f32x2 %0, %1, %2, %3;" : "=l"(d) : "l"(a), "l"(b), "l"(c));
    return d;
}
__device__ __forceinline__ u64 pack2(float x) {
    u64 d; asm("mov.b64 %0, {%1, %1};" : "=l"(d) : "f"(x));
    return d;
}
__device__ __forceinline__ float2 unpk(u64 v) {
    float2 r; asm("mov.b64 {%0, %1}, %2;" : "=f"(r.x), "=f"(r.y) : "l"(v));
    return r;
}

__device__ __forceinline__ float ang_sim(float d) {
    d *= 0.99999f;
    d = fminf(fmaxf(d, -1.f), 1.f);
    return 1.f - acosf(d) * INV_PI;
}

// ---------------- K1: features + row-normalize + cross-modal dots (fused) ----
__global__ void prep_kernel(const float* __restrict__ xa,
                            const float* __restrict__ xv,
                            const float* __restrict__ xt) {
    int w = threadIdx.x >> 5, lane = threadIdx.x & 31;
    int a = blockIdx.x * 8 + w;           // < 2048
    const float* pa = xa + a * Hd;
    const float* pv = xv + a * Hd;
    const float* pt = xt + a * Hd;
    float va[7], vv[7], vt[7];
    float saa = 0.f, svv = 0.f, stt = 0.f, sav = 0.f, sat = 0.f, svt = 0.f;
#pragma unroll
    for (int i = 0; i < 7; i++) {
        int c = lane + i * 32;
        float A = (c < Hd) ? pa[c] : 0.f;
        float V = (c < Hd) ? pv[c] : 0.f;
        float T = (c < Hd) ? pt[c] : 0.f;
        va[i] = A; vv[i] = V; vt[i] = T;
        saa = fmaf(A, A, saa); svv = fmaf(V, V, svv); stt = fmaf(T, T, stt);
        sav = fmaf(A, V, sav); sat = fmaf(A, T, sat); svt = fmaf(V, T, svt);
    }
#pragma unroll
    for (int o = 16; o; o >>= 1) {
        saa += __shfl_xor_sync(0xffffffffu, saa, o);
        svv += __shfl_xor_sync(0xffffffffu, svv, o);
        stt += __shfl_xor_sync(0xffffffffu, stt, o);
        sav += __shfl_xor_sync(0xffffffffu, sav, o);
        sat += __shfl_xor_sync(0xffffffffu, sat, o);
        svt += __shfl_xor_sync(0xffffffffu, svt, o);
    }
    float ra = rsqrtf(saa), rv = rsqrtf(svv), rt = rsqrtf(stt);
#pragma unroll
    for (int i = 0; i < 7; i++) {
        int c = lane + i * 32;
        if (c < Hd) {
            g_feats[(0 * An + a) * Hd + c] = va[i];
            g_feats[(1 * An + a) * Hd + c] = vv[i];
            g_feats[(2 * An + a) * Hd + c] = vt[i];
            g_nrm  [(0 * An + a) * Hd + c] = va[i] * ra;
            g_nrm  [(1 * An + a) * Hd + c] = vv[i] * rv;
            g_nrm  [(2 * An + a) * Hd + c] = vt[i] * rt;
        }
    }
    if (lane == 0) {
        g_cdot[0 * An + a] = ang_sim(sav * ra * rv);
        g_cdot[1 * An + a] = ang_sim(sat * ra * rt);
        g_cdot[2 * An + a] = ang_sim(svt * rv * rt);
    }
}

// ---------------- K2: intra-dialogue 64x64 gram blocks (angular sim) ---------
__global__ void intra_kernel() {
    int mb = blockIdx.x;                  // 0..95
    const float* blk = g_nrm + mb * 64 * Hd;
    __shared__ float s[40][68];           // s[kk][row]
    int t = threadIdx.x;
    int tx = t & 15, ty = t >> 4;
    float acc[4][4] = {};
    for (int h0c = 0; h0c < Hd; h0c += 40) {
        __syncthreads();
#pragma unroll
        for (int k = 0; k < 10; k++) {
            int idx = t + k * 256;        // < 2560
            int r = idx / 40, c = idx % 40;
            s[c][r] = blk[r * Hd + h0c + c];
        }
        __syncthreads();
#pragma unroll 4
        for (int kk = 0; kk < 40; kk++) {
            float a[4], b[4];
#pragma unroll
            for (int ii = 0; ii < 4; ii++) a[ii] = s[kk][ty * 4 + ii];
#pragma unroll
            for (int jj = 0; jj < 4; jj++) b[jj] = s[kk][tx * 4 + jj];
#pragma unroll
            for (int ii = 0; ii < 4; ii++)
#pragma unroll
                for (int jj = 0; jj < 4; jj++)
                    acc[ii][jj] = fmaf(a[ii], b[jj], acc[ii][jj]);
        }
    }
#pragma unroll
    for (int ii = 0; ii < 4; ii++)
#pragma unroll
        for (int jj = 0; jj < 4; jj++)
            g_intra[mb * 4096 + (ty * 4 + ii) * 64 + (tx * 4 + jj)] = ang_sim(acc[ii][jj]);
}

// ---------------- K3: degrees -> dinv (warp per row) ----------------
__global__ void degree_kernel() {
    int w = threadIdx.x >> 5, lane = threadIdx.x & 31;
    int u = blockIdx.x * 8 + w;           // < 6144
    int m = u >> 11, a = u & 2047, l = u & 63;
    int mb = u >> 6;
    const float* row = g_intra + mb * 4096 + l * 64;
    float s = row[lane] + row[lane + 32];
#pragma unroll
    for (int o = 16; o; o >>= 1) s += __shfl_xor_sync(0xffffffffu, s, o);
    if (lane == 0) {
        float c0 = g_cdot[a], c1 = g_cdot[An + a], c2 = g_cdot[2 * An + a];
        s += (m == 0) ? (c0 + c1) : (m == 1) ? (c0 + c2) : (c1 + c2);
        g_dinv[u] = rsqrtf(s);
    }
}

// ---------------- K4: scale cross weights ----------------
__global__ void scale_cross_kernel() {
    int idx = blockIdx.x * 256 + threadIdx.x;  // < 12288
    int pr = idx >> 11, a = idx & 2047;
    const int mt[6] = {0,0,1,1,2,2};
    const int nt[6] = {1,2,0,2,0,1};
    const int dt[6] = {0,1,0,2,1,2};
    int m = mt[pr], n = nt[pr];
    g_crossw[(m * 3 + n) * An + a] =
        g_cdot[dt[pr] * An + a] * g_dinv[m * An + a] * g_dinv[n * An + a];
}

// ---------------- K5: structured adj @ h (dinv fused, FFMA2) ----------------
__global__ void adjmul_kernel() {
    int mb = blockIdx.x;                      // 0..95
    int m = mb >> 5, b = mb & 31;
    __shared__ float sd[64];
    __shared__ float si[64][65];              // normalized intra block [i][j]
    __shared__ __align__(16) float hs[64][40];// h chunk [j][cc]
    int t = threadIdx.x;
    if (t < 64) sd[t] = g_dinv[mb * 64 + t];
    __syncthreads();
#pragma unroll
    for (int k = 0; k < 16; k++) {
        int idx = t + k * 256;                // < 4096
        int ii = idx >> 6, jj = idx & 63;
        si[ii][jj] = g_intra[mb * 4096 + idx] * sd[ii] * sd[jj];
    }
    int i = t & 63, cq = t >> 6;              // cq 0..3
    int a = b * 64 + i;
    int n0 = (m == 0) ? 1 : 0;
    int n1 = (m == 2) ? 1 : 2;
    float w0 = g_crossw[(m * 3 + n0) * An + a];
    float w1 = g_crossw[(m * 3 + n1) * An + a];
    const float* h0r = g_h + (n0 * An + a) * Hd;
    const float* h1r = g_h + (n1 * An + a) * Hd;
    int rowbase = m * An + b * 64;
    for (int cc = 0; cc < Hd; cc += 40) {
        __syncthreads();
#pragma unroll
        for (int k = 0; k < 10; k++) {
            int idx = t + k * 256;            // < 2560
            int r = idx / 40, c2 = idx % 40;
            hs[r][c2] = g_h[(rowbase + r) * Hd + cc + c2];
        }
        __syncthreads();
        u64 acc[5] = {0ull, 0ull, 0ull, 0ull, 0ull};
#pragma unroll 8
        for (int j = 0; j < 64; j++) {
            u64 aij = pack2(si[i][j]);
            const u64* hp = reinterpret_cast<const u64*>(&hs[j][cq * 10]);
#pragma unroll
            for (int q = 0; q < 5; q++) acc[q] = ffma2(aij, hp[q], acc[q]);
        }
#pragma unroll
        for (int q = 0; q < 5; q++) {
            int c = cc + cq * 10 + 2 * q;
            float2 v = unpk(acc[q]);
            float2 a0 = *(const float2*)&h0r[c];
            float2 a1 = *(const float2*)&h1r[c];
            float2 o;
            o.x = v.x + w0 * a0.x + w1 * a1.x;
            o.y = v.y + w0 * a0.y + w1 * a1.y;
            *(float2*)&g_hi[(rowbase + i) * Hd + c] = o;
        }
    }
}

// ---------------- packed-FMA skinny GEMM: C[M,200] = epi(A[M,K] @ W[K,200]) --
// BM=64, BN=200, 128 threads; thread tile = 2 rows x 25 col-pairs (FFMA2).
// Register-staged software pipeline over KC=16 chunks.
// MODE 0: fc0   (A=feats, K=200, relu+bias, writes g_h AND g_h0)
// MODE 1: conv  (A=[hi|h0], K=400, gcnii epilogue, writes g_h)
// MODE 2: tm    (A=[feats_m|h_m], K=400, relu+bias, z=modality, writes g_hx)
// MODE 3: cross (A=[hx_i|hx_j|hx_i*hx_j], K=600, sigmoid+bias, z=pair, writes g_z)
template<int MODE>
__global__ void __launch_bounds__(128) gemm2(const float* __restrict__ Wg,
                                             const float* __restrict__ biasg,
                                             float beta) {
    constexpr int K = (MODE == 0) ? 200 : ((MODE == 3) ? 600 : 400);
    constexpr int NCH = (K + 15) / 16;
    const int z = blockIdx.z;
    const float *A0, *A1 = nullptr;
    float *C, *C2 = nullptr;
    const float* bias = nullptr;
    if (MODE == 0)      { A0 = g_feats; C = g_h; C2 = g_h0; bias = biasg; }
    else if (MODE == 1) { A0 = g_hi; A1 = g_h0; C = g_h; }
    else if (MODE == 2) { A0 = g_feats + z * AH; A1 = g_h + z * AH;
                          C = g_hx + z * AH; bias = biasg + z * Hd; }
    else                { int ii = z >> 1; int jj = c_jtab[z];
                          A0 = g_hx + ii * AH; A1 = g_hx + jj * AH;
                          C = g_z + z * AH; bias = biasg + z * Hd; }
    const float* W = Wg + z * K * Hd;

    __shared__ __align__(16) float Bs[16 * 200];
    __shared__ float As[64][17];
    int t = threadIdx.x;
    int p = t >> 2, cg = t & 3;               // row-pair 0..31, col group 0..3
    int base = cg * 50;
    int row0 = blockIdx.y * 64;

    u64 acc0[25], acc1[25];
#pragma unroll
    for (int q = 0; q < 25; q++) { acc0[q] = 0ull; acc1[q] = 0ull; }

    // staging register layout
    int wr = t >> 3, wc = (t & 7) * 25;       // B: row-in-chunk, col base
    int ar = t >> 1;                          // A: row 0..63
    int akb = (t & 1) * 8;                    // A: kk base
    int grow = row0 + ar;

    auto loadA = [&](int k) -> float {
        if (k >= K) return 0.f;
        if (MODE == 3) {
            if (k < 200)      return A0[grow * Hd + k];
            else if (k < 400) return A1[grow * Hd + k - 200];
            else { int kr = k - 400; return A0[grow * Hd + kr] * A1[grow * Hd + kr]; }
        } else if (K == 400) {
            return (k < 200) ? A0[grow * Hd + k] : A1[grow * Hd + k - 200];
        } else {
            return A0[grow * Hd + k];
        }
    };

    float wreg[25], areg[8];
    {   // stage chunk 0
        int k = wr;
#pragma unroll
        for (int j = 0; j < 25; j++) wreg[j] = (k < K) ? W[k * Hd + wc + j] : 0.f;
#pragma unroll
        for (int ld = 0; ld < 8; ld++) areg[ld] = loadA(akb + ld);
    }

    for (int ch = 0; ch < NCH; ch++) {
        // commit staged regs to smem
#pragma unroll
        for (int j = 0; j < 25; j++) Bs[wr * 200 + wc + j] = wreg[j];
#pragma unroll
        for (int ld = 0; ld < 8; ld++) As[ar][akb + ld] = areg[ld];
        __syncthreads();
        if (ch + 1 < NCH) {                   // prefetch next chunk (hides LDG)
            int k0n = (ch + 1) * 16;
            int k = k0n + wr;
#pragma unroll
            for (int j = 0; j < 25; j++) wreg[j] = (k < K) ? W[k * Hd + wc + j] : 0.f;
#pragma unroll
            for (int ld = 0; ld < 8; ld++) areg[ld] = loadA(k0n + akb + ld);
        }
#pragma unroll 4
        for (int kk = 0; kk < 16; kk++) {
            u64 pa0 = pack2(As[2 * p][kk]);
            u64 pa1 = pack2(As[2 * p + 1][kk]);
            const u64* bp = reinterpret_cast<const u64*>(&Bs[kk * 200 + base]);
#pragma unroll
            for (int q = 0; q < 25; q++) {
                u64 bq = bp[q];
                acc0[q] = ffma2(pa0, bq, acc0[q]);
                acc1[q] = ffma2(pa1, bq, acc1[q]);
            }
        }
        __syncthreads();
    }

    // epilogue
    int r0 = row0 + 2 * p, r1 = r0 + 1;
    float omb = 1.f - beta;
#pragma unroll
    for (int q = 0; q < 25; q++) {
        int c = base + 2 * q;
        float2 v0 = unpk(acc0[q]);
        float2 v1 = unpk(acc1[q]);
        if (MODE == 0) {
            float2 bb = *(const float2*)&bias[c];
            v0.x = fmaxf(v0.x + bb.x, 0.f); v0.y = fmaxf(v0.y + bb.y, 0.f);
            v1.x = fmaxf(v1.x + bb.x, 0.f); v1.y = fmaxf(v1.y + bb.y, 0.f);
            *(float2*)&C [r0 * Hd + c] = v0; *(float2*)&C2[r0 * Hd + c] = v0;
            *(float2*)&C [r1 * Hd + c] = v1; *(float2*)&C2[r1 * Hd + c] = v1;
        } else if (MODE == 1) {
            float2 hi0 = *(const float2*)&g_hi[r0 * Hd + c];
            float2 h00 = *(const float2*)&g_h0[r0 * Hd + c];
            float2 hi1 = *(const float2*)&g_hi[r1 * Hd + c];
            float2 h01 = *(const float2*)&g_h0[r1 * Hd + c];
            float2 o;
            o.x = fmaxf(beta * v0.x + omb * (0.9f * hi0.x + 0.1f * h00.x), 0.f);
            o.y = fmaxf(beta * v0.y + omb * (0.9f * hi0.y + 0.1f * h00.y), 0.f);
            *(float2*)&C[r0 * Hd + c] = o;
            o.x = fmaxf(beta * v1.x + omb * (0.9f * hi1.x + 0.1f * h01.x), 0.f);
            o.y = fmaxf(beta * v1.y + omb * (0.9f * hi1.y + 0.1f * h01.y), 0.f);
            *(float2*)&C[r1 * Hd + c] = o;
        } else if (MODE == 2) {
            float2 bb = *(const float2*)&bias[c];
            v0.x = fmaxf(v0.x + bb.x, 0.f); v0.y = fmaxf(v0.y + bb.y, 0.f);
            v1.x = fmaxf(v1.x + bb.x, 0.f); v1.y = fmaxf(v1.y + bb.y, 0.f);
            *(float2*)&C[r0 * Hd + c] = v0;
            *(float2*)&C[r1 * Hd + c] = v1;
        } else {
            float2 bb = *(const float2*)&bias[c];
            v0.x = 1.f / (1.f + __expf(-(v0.x + bb.x)));
            v0.y = 1.f / (1.f + __expf(-(v0.y + bb.y)));
            v1.x = 1.f / (1.f + __expf(-(v1.x + bb.x)));
            v1.y = 1.f / (1.f + __expf(-(v1.y + bb.y)));
            *(float2*)&C[r0 * Hd + c] = v0;
            *(float2*)&C[r1 * Hd + c] = v1;
        }
    }
}

// ---------------- K6: gated combine + final logits (fused) ----------------
__global__ void joint_kernel(const float* __restrict__ uw,
                             const float* __restrict__ ub,
                             float* __restrict__ out) {
    __shared__ float su[3600];
    __shared__ float sb[6];
    int t = threadIdx.x;
    for (int i = t; i < 3600; i += 256) su[i] = uw[i];
    if (t < 6) sb[t] = ub[t] + ub[6 + t] + ub[12 + t];
    __syncthreads();
    int w = t >> 5, lane = t & 31;
    int a = blockIdx.x * 8 + w;                   // < 2048
    float acc[6] = {};
    const float* hx0 = g_hx + 0 * AH + a * Hd;
    const float* hx1 = g_hx + 1 * AH + a * Hd;
    const float* hx2 = g_hx + 2 * AH + a * Hd;
    const float* zb  = g_z + a * Hd;
    for (int c = lane; c < Hd; c += 32) {
        float x0 = hx0[c], x1 = hx1[c], x2 = hx2[c];
        float z0 = zb[0 * AH + c], z1 = zb[1 * AH + c], z2 = zb[2 * AH + c];
        float z3 = zb[3 * AH + c], z4 = zb[4 * AH + c], z5 = zb[5 * AH + c];
        float o0 = z0 * x0 + (1.f - z0) * x1 + z1 * x0 + (1.f - z1) * x2;
        float o1 = z2 * x1 + (1.f - z2) * x0 + z3 * x1 + (1.f - z3) * x2;
        float o2 = z4 * x2 + (1.f - z4) * x0 + z5 * x2 + (1.f - z5) * x1;
#pragma unroll
        for (int tg = 0; tg < 6; tg++)
            acc[tg] += o0 * su[c * 6 + tg]
                     + o1 * su[1200 + c * 6 + tg]
                     + o2 * su[2400 + c * 6 + tg];
    }
#pragma unroll
    for (int o = 16; o; o >>= 1)
#pragma unroll
        for (int tg = 0; tg < 6; tg++)
            acc[tg] += __shfl_xor_sync(0xffffffffu, acc[tg], o);
    if (lane == 0)
#pragma unroll
        for (int tg = 0; tg < 6; tg++)
            out[a * 6 + tg] = acc[tg] + sb[tg];
}

// ---------------- host launcher ----------------
extern "C" void kernel_launch(void* const* d_in, const int* in_sizes, int n_in,
                              void* d_out, int out_size) {
    const float* x_a     = (const float*)d_in[0];
    const float* x_v     = (const float*)d_in[1];
    const float* x_t     = (const float*)d_in[2];
    const float* fc0_w   = (const float*)d_in[3];
    const float* fc0_b   = (const float*)d_in[4];
    const float* conv_w  = (const float*)d_in[5];
    const float* tm_w    = (const float*)d_in[6];
    const float* tm_b    = (const float*)d_in[7];
    const float* cross_w = (const float*)d_in[8];
    const float* cross_b = (const float*)d_in[9];
    const float* uni_w   = (const float*)d_in[10];
    const float* uni_b   = (const float*)d_in[11];
    float* out = (float*)d_out;

    const float beta0 = 0.40546510810816438f;  // log(1.5)
    const float beta1 = 0.22314355131420976f;  // log(1.25)

    prep_kernel<<<256, 256>>>(x_a, x_v, x_t);
    intra_kernel<<<96, 256>>>();
    degree_kernel<<<768, 256>>>();
    scale_cross_kernel<<<48, 256>>>();

    gemm2<0><<<dim3(1, 96, 1), 128>>>(fc0_w, fc0_b, 0.f);

    adjmul_kernel<<<96, 256>>>();
    gemm2<1><<<dim3(1, 96, 1), 128>>>(conv_w, nullptr, beta0);
    adjmul_kernel<<<96, 256>>>();
    gemm2<1><<<dim3(1, 96, 1), 128>>>(conv_w + 400 * Hd, nullptr, beta1);

    gemm2<2><<<dim3(1, 32, 3), 128>>>(tm_w, tm_b, 0.f);
    gemm2<3><<<dim3(1, 32, 6), 128>>>(cross_w, cross_b, 0.f);

    joint_kernel<<<256, 256>>>(uni_w, uni_b, out);
}

// round 3
// speedup vs baseline: 1.7685x; 1.1151x over previous
#include <cuda_runtime.h>
#include <math.h>

typedef unsigned long long u64;

// ---------------- problem constants ----------------
#define Hd   200
#define An   2048            // nodes per modality
#define Nn   6144            // total nodes
#define AH   (An*Hd)         // 409600
#define INV_PI 0.31830988618379067f

// ---------------- scratch (static device globals; no allocs) ----------------
__device__ __align__(16) float g_feats [Nn*Hd];
__device__ __align__(16) float g_nrm   [Nn*Hd];
__device__ __align__(16) float g_intra [96*4096];  // 96 blocks of 64x64
__device__ __align__(16) float g_cdot  [3*An];
__device__ __align__(16) float g_dinv  [Nn];
__device__ __align__(16) float g_h     [Nn*Hd];
__device__ __align__(16) float g_h0    [Nn*Hd];
__device__ __align__(16) float g_hi    [Nn*Hd];
__device__ __align__(16) float g_hx    [3*AH];
__device__ __align__(16) float g_z     [6*AH];

__constant__ int c_jtab[6] = {1,2,0,2,0,1}; // partner modality per gate pair

// ---------------- helpers ----------------
__device__ __forceinline__ u64 ffma2(u64 a, u64 b, u64 c) {
    u64 d; asm("fma.rn.f32x2 %0, %1, %2, %3;" : "=l"(d) : "l"(a), "l"(b), "l"(c));
    return d;
}
__device__ __forceinline__ u64 pack2(float x) {
    u64 d; asm("mov.b64 %0, {%1, %1};" : "=l"(d) : "f"(x));
    return d;
}
__device__ __forceinline__ float2 unpk(u64 v) {
    float2 r; asm("mov.b64 {%0, %1}, %2;" : "=f"(r.x), "=f"(r.y) : "l"(v));
    return r;
}
__device__ __forceinline__ unsigned smem_u32(const void* p) {
    return (unsigned)__cvta_generic_to_shared(p);
}
__device__ __forceinline__ void cpasync16(unsigned dst, const void* src) {
    asm volatile("cp.async.cg.shared.global [%0], [%1], 16;" :: "r"(dst), "l"(src));
}
__device__ __forceinline__ float ang_sim(float d) {
    d *= 0.99999f;
    d = fminf(fmaxf(d, -1.f), 1.f);
    return 1.f - acosf(d) * INV_PI;
}

// ---------------- K1: features + row-normalize + cross-modal dots (fused) ----
__global__ void prep_kernel(const float* __restrict__ xa,
                            const float* __restrict__ xv,
                            const float* __restrict__ xt) {
    int w = threadIdx.x >> 5, lane = threadIdx.x & 31;
    int a = blockIdx.x * 8 + w;           // < 2048
    const float* pa = xa + a * Hd;
    const float* pv = xv + a * Hd;
    const float* pt = xt + a * Hd;
    float va[7], vv[7], vt[7];
    float saa = 0.f, svv = 0.f, stt = 0.f, sav = 0.f, sat = 0.f, svt = 0.f;
#pragma unroll
    for (int i = 0; i < 7; i++) {
        int c = lane + i * 32;
        float A = (c < Hd) ? pa[c] : 0.f;
        float V = (c < Hd) ? pv[c] : 0.f;
        float T = (c < Hd) ? pt[c] : 0.f;
        va[i] = A; vv[i] = V; vt[i] = T;
        saa = fmaf(A, A, saa); svv = fmaf(V, V, svv); stt = fmaf(T, T, stt);
        sav = fmaf(A, V, sav); sat = fmaf(A, T, sat); svt = fmaf(V, T, svt);
    }
#pragma unroll
    for (int o = 16; o; o >>= 1) {
        saa += __shfl_xor_sync(0xffffffffu, saa, o);
        svv += __shfl_xor_sync(0xffffffffu, svv, o);
        stt += __shfl_xor_sync(0xffffffffu, stt, o);
        sav += __shfl_xor_sync(0xffffffffu, sav, o);
        sat += __shfl_xor_sync(0xffffffffu, sat, o);
        svt += __shfl_xor_sync(0xffffffffu, svt, o);
    }
    float ra = rsqrtf(saa), rv = rsqrtf(svv), rt = rsqrtf(stt);
#pragma unroll
    for (int i = 0; i < 7; i++) {
        int c = lane + i * 32;
        if (c < Hd) {
            g_feats[(0 * An + a) * Hd + c] = va[i];
            g_feats[(1 * An + a) * Hd + c] = vv[i];
            g_feats[(2 * An + a) * Hd + c] = vt[i];
            g_nrm  [(0 * An + a) * Hd + c] = va[i] * ra;
            g_nrm  [(1 * An + a) * Hd + c] = vv[i] * rv;
            g_nrm  [(2 * An + a) * Hd + c] = vt[i] * rt;
        }
    }
    if (lane == 0) {
        g_cdot[0 * An + a] = ang_sim(sav * ra * rv);
        g_cdot[1 * An + a] = ang_sim(sat * ra * rt);
        g_cdot[2 * An + a] = ang_sim(svt * rv * rt);
    }
}

// ---------------- K2: intra 64x64 gram blocks + degree/dinv (fused) ---------
__global__ void intra_kernel() {
    int mb = blockIdx.x;                  // 0..95
    int m = mb >> 5;
    const float* blk = g_nrm + mb * 64 * Hd;
    __shared__ float s[40][68];           // s[kk][row]
    __shared__ float rs[64];
    int t = threadIdx.x;
    int tx = t & 15, ty = t >> 4;
    if (t < 64) rs[t] = 0.f;
    float acc[4][4] = {};
    for (int h0c = 0; h0c < Hd; h0c += 40) {
        __syncthreads();
#pragma unroll
        for (int k = 0; k < 10; k++) {
            int idx = t + k * 256;        // < 2560
            int r = idx / 40, c = idx % 40;
            s[c][r] = blk[r * Hd + h0c + c];
        }
        __syncthreads();
#pragma unroll 4
        for (int kk = 0; kk < 40; kk++) {
            float a[4], b[4];
#pragma unroll
            for (int ii = 0; ii < 4; ii++) a[ii] = s[kk][ty * 4 + ii];
#pragma unroll
            for (int jj = 0; jj < 4; jj++) b[jj] = s[kk][tx * 4 + jj];
#pragma unroll
            for (int ii = 0; ii < 4; ii++)
#pragma unroll
                for (int jj = 0; jj < 4; jj++)
                    acc[ii][jj] = fmaf(a[ii], b[jj], acc[ii][jj]);
        }
    }
#pragma unroll
    for (int ii = 0; ii < 4; ii++) {
        float rsum = 0.f;
#pragma unroll
        for (int jj = 0; jj < 4; jj++) {
            float v = ang_sim(acc[ii][jj]);
            g_intra[mb * 4096 + (ty * 4 + ii) * 64 + (tx * 4 + jj)] = v;
            rsum += v;
        }
        atomicAdd(&rs[ty * 4 + ii], rsum);
    }
    __syncthreads();
    if (t < 64) {
        int a = (mb & 31) * 64 + t;
        float c0 = g_cdot[a], c1 = g_cdot[An + a], c2 = g_cdot[2 * An + a];
        float ssum = rs[t] + ((m == 0) ? (c0 + c1) : (m == 1) ? (c0 + c2) : (c1 + c2));
        g_dinv[mb * 64 + t] = rsqrtf(ssum);
    }
}

// ---------------- K3: structured adj @ h (dinv + crossw inline, FFMA2) -------
__global__ void adjmul_kernel() {
    int mb = blockIdx.x;                      // 0..95
    int m = mb >> 5, b = mb & 31;
    __shared__ float sd[64];
    __shared__ float si[64][65];              // normalized intra block [i][j]
    __shared__ __align__(16) float hs[64][40];// h chunk [j][cc]
    int t = threadIdx.x;
    if (t < 64) sd[t] = g_dinv[mb * 64 + t];
    __syncthreads();
#pragma unroll
    for (int k = 0; k < 16; k++) {
        int idx = t + k * 256;                // < 4096
        int ii = idx >> 6, jj = idx & 63;
        si[ii][jj] = g_intra[mb * 4096 + idx] * sd[ii] * sd[jj];
    }
    int i = t & 63, cq = t >> 6;              // cq 0..3
    int a = b * 64 + i;
    int n0 = (m == 0) ? 1 : 0;
    int n1 = (m == 2) ? 1 : 2;
    float dm = g_dinv[m * An + a];
    float w0 = g_cdot[(m + n0 - 1) * An + a] * dm * g_dinv[n0 * An + a];
    float w1 = g_cdot[(m + n1 - 1) * An + a] * dm * g_dinv[n1 * An + a];
    const float* h0r = g_h + (n0 * An + a) * Hd;
    const float* h1r = g_h + (n1 * An + a) * Hd;
    int rowbase = m * An + b * 64;
    for (int cc = 0; cc < Hd; cc += 40) {
        __syncthreads();
#pragma unroll
        for (int k = 0; k < 10; k++) {
            int idx = t + k * 256;            // < 2560
            int r = idx / 40, c2 = idx % 40;
            hs[r][c2] = g_h[(rowbase + r) * Hd + cc + c2];
        }
        __syncthreads();
        u64 acc[5] = {0ull, 0ull, 0ull, 0ull, 0ull};
#pragma unroll 8
        for (int j = 0; j < 64; j++) {
            u64 aij = pack2(si[i][j]);
            const u64* hp = reinterpret_cast<const u64*>(&hs[j][cq * 10]);
#pragma unroll
            for (int q = 0; q < 5; q++) acc[q] = ffma2(aij, hp[q], acc[q]);
        }
#pragma unroll
        for (int q = 0; q < 5; q++) {
            int c = cc + cq * 10 + 2 * q;
            float2 v = unpk(acc[q]);
            float2 a0 = *(const float2*)&h0r[c];
            float2 a1 = *(const float2*)&h1r[c];
            float2 o;
            o.x = v.x + w0 * a0.x + w1 * a1.x;
            o.y = v.y + w0 * a0.y + w1 * a1.y;
            *(float2*)&g_hi[(rowbase + i) * Hd + c] = o;
        }
    }
}

// ---------------- packed-FMA skinny GEMM: C[M,200] = epi(A[M,K] @ W[K,200]) --
// BM=64, BN=200, 128 threads; thread = 2 rows x 25 col-pairs.
// A in registers (per-thread own rows), B via cp.async double-buffered KC=8.
// MODE 0: fc0   (K=200, relu+bias, writes g_h AND g_h0)
// MODE 1: conv  (K=400 [hi|h0], gcnii epilogue, writes g_h)
// MODE 2: tm    (K=400 [feats_m|h_m], relu+bias, z=modality, writes g_hx)
// MODE 3: cross (K=600 [hx_i|hx_j|hx_i*hx_j], sigmoid+bias, z=pair, writes g_z)
template<int MODE>
__global__ void __launch_bounds__(128) gemm2(const float* __restrict__ Wg,
                                             const float* __restrict__ biasg,
                                             float beta) {
    constexpr int K = (MODE == 0) ? 200 : ((MODE == 3) ? 600 : 400);
    constexpr int NCH = K / 8;
    const int z = blockIdx.z;
    const float *A0, *A1 = nullptr;
    float *C, *C2 = nullptr;
    const float* bias = nullptr;
    if (MODE == 0)      { A0 = g_feats; C = g_h; C2 = g_h0; bias = biasg; }
    else if (MODE == 1) { A0 = g_hi; A1 = g_h0; C = g_h; }
    else if (MODE == 2) { A0 = g_feats + z * AH; A1 = g_h + z * AH;
                          C = g_hx + z * AH; bias = biasg + z * Hd; }
    else                { int ii = z >> 1; int jj = c_jtab[z];
                          A0 = g_hx + ii * AH; A1 = g_hx + jj * AH;
                          C = g_z + z * AH; bias = biasg + z * Hd; }
    const float* W = Wg + z * K * Hd;

    __shared__ __align__(16) float Bs[2][8 * 200];
    int t = threadIdx.x;
    int p = t >> 2, cg = t & 3;
    int base = cg * 50;
    int row0 = blockIdx.y * 64;
    int r0 = row0 + 2 * p, r1 = r0 + 1;

    u64 acc0[25], acc1[25];
#pragma unroll
    for (int q = 0; q < 25; q++) { acc0[q] = 0ull; acc1[q] = 0ull; }

    unsigned bsbase0 = smem_u32(&Bs[0][0]);
    unsigned bsbase1 = smem_u32(&Bs[1][0]);

    auto issueB = [&](int ch, int buf) {
        const float* src = W + ch * 8 * Hd;
        unsigned d = buf ? bsbase1 : bsbase0;
#pragma unroll
        for (int i = 0; i < 4; i++) {
            int idx = t + i * 128;
            if (idx < 400) cpasync16(d + idx * 16, src + idx * 4);
        }
        asm volatile("cp.async.commit_group;");
    };

    auto loadA8 = [&](int r, int k0, float4& x, float4& y) {
        if (MODE == 0) {
            const float4* pp = (const float4*)(A0 + r * Hd + k0);
            x = pp[0]; y = pp[1];
        } else if (MODE != 3) {
            const float* Ax = (k0 < 200) ? (A0 + r * Hd + k0)
                                         : (A1 + r * Hd + (k0 - 200));
            const float4* pp = (const float4*)Ax;
            x = pp[0]; y = pp[1];
        } else {
            if (k0 < 200) {
                const float4* pp = (const float4*)(A0 + r * Hd + k0);
                x = pp[0]; y = pp[1];
            } else if (k0 < 400) {
                const float4* pp = (const float4*)(A1 + r * Hd + (k0 - 200));
                x = pp[0]; y = pp[1];
            } else {
                int kr = k0 - 400;
                const float4* pu = (const float4*)(A0 + r * Hd + kr);
                const float4* pv = (const float4*)(A1 + r * Hd + kr);
                float4 u0 = pu[0], u1 = pu[1], v0 = pv[0], v1 = pv[1];
                x.x = u0.x * v0.x; x.y = u0.y * v0.y; x.z = u0.z * v0.z; x.w = u0.w * v0.w;
                y.x = u1.x * v1.x; y.y = u1.y * v1.y; y.z = u1.z * v1.z; y.w = u1.w * v1.w;
            }
        }
    };

    float4 aC[4], aN[4];   // [0..1]=row0 k0..k0+7, [2..3]=row1
    issueB(0, 0);
    loadA8(r0, 0, aC[0], aC[1]);
    loadA8(r1, 0, aC[2], aC[3]);

    for (int ch = 0; ch < NCH; ch++) {
        int buf = ch & 1;
        if (ch + 1 < NCH) {
            issueB(ch + 1, buf ^ 1);
            int k0n = (ch + 1) * 8;
            loadA8(r0, k0n, aN[0], aN[1]);
            loadA8(r1, k0n, aN[2], aN[3]);
            asm volatile("cp.async.wait_group 1;");
        } else {
            asm volatile("cp.async.wait_group 0;");
        }
        __syncthreads();
        const float* fBs = &Bs[buf][0];
#pragma unroll
        for (int kk = 0; kk < 8; kk++) {
            float a0v = ((const float*)&aC[kk >> 2])[kk & 3];
            float a1v = ((const float*)&aC[2 + (kk >> 2)])[kk & 3];
            u64 pa0 = pack2(a0v);
            u64 pa1 = pack2(a1v);
            const u64* bp = reinterpret_cast<const u64*>(fBs + kk * 200 + base);
#pragma unroll
            for (int q = 0; q < 25; q++) {
                u64 bq = bp[q];
                acc0[q] = ffma2(pa0, bq, acc0[q]);
                acc1[q] = ffma2(pa1, bq, acc1[q]);
            }
        }
#pragma unroll
        for (int i = 0; i < 4; i++) aC[i] = aN[i];
        __syncthreads();
    }

    // epilogue
    float omb = 1.f - beta;
#pragma unroll
    for (int q = 0; q < 25; q++) {
        int c = base + 2 * q;
        float2 v0 = unpk(acc0[q]);
        float2 v1 = unpk(acc1[q]);
        if (MODE == 0) {
            float2 bb = *(const float2*)&bias[c];
            v0.x = fmaxf(v0.x + bb.x, 0.f); v0.y = fmaxf(v0.y + bb.y, 0.f);
            v1.x = fmaxf(v1.x + bb.x, 0.f); v1.y = fmaxf(v1.y + bb.y, 0.f);
            *(float2*)&C [r0 * Hd + c] = v0; *(float2*)&C2[r0 * Hd + c] = v0;
            *(float2*)&C [r1 * Hd + c] = v1; *(float2*)&C2[r1 * Hd + c] = v1;
        } else if (MODE == 1) {
            float2 hi0 = *(const float2*)&g_hi[r0 * Hd + c];
            float2 h00 = *(const float2*)&g_h0[r0 * Hd + c];
            float2 hi1 = *(const float2*)&g_hi[r1 * Hd + c];
            float2 h01 = *(const float2*)&g_h0[r1 * Hd + c];
            float2 o;
            o.x = fmaxf(beta * v0.x + omb * (0.9f * hi0.x + 0.1f * h00.x), 0.f);
            o.y = fmaxf(beta * v0.y + omb * (0.9f * hi0.y + 0.1f * h00.y), 0.f);
            *(float2*)&C[r0 * Hd + c] = o;
            o.x = fmaxf(beta * v1.x + omb * (0.9f * hi1.x + 0.1f * h01.x), 0.f);
            o.y = fmaxf(beta * v1.y + omb * (0.9f * hi1.y + 0.1f * h01.y), 0.f);
            *(float2*)&C[r1 * Hd + c] = o;
        } else if (MODE == 2) {
            float2 bb = *(const float2*)&bias[c];
            v0.x = fmaxf(v0.x + bb.x, 0.f); v0.y = fmaxf(v0.y + bb.y, 0.f);
            v1.x = fmaxf(v1.x + bb.x, 0.f); v1.y = fmaxf(v1.y + bb.y, 0.f);
            *(float2*)&C[r0 * Hd + c] = v0;
            *(float2*)&C[r1 * Hd + c] = v1;
        } else {
            float2 bb = *(const float2*)&bias[c];
            v0.x = 1.f / (1.f + __expf(-(v0.x + bb.x)));
            v0.y = 1.f / (1.f + __expf(-(v0.y + bb.y)));
            v1.x = 1.f / (1.f + __expf(-(v1.x + bb.x)));
            v1.y = 1.f / (1.f + __expf(-(v1.y + bb.y)));
            *(float2*)&C[r0 * Hd + c] = v0;
            *(float2*)&C[r1 * Hd + c] = v1;
        }
    }
}

// ---------------- K4: gated combine + final logits (fused) ----------------
__global__ void joint_kernel(const float* __restrict__ uw,
                             const float* __restrict__ ub,
                             float* __restrict__ out) {
    __shared__ float su[3600];
    __shared__ float sb[6];
    int t = threadIdx.x;
    for (int i = t; i < 3600; i += 256) su[i] = uw[i];
    if (t < 6) sb[t] = ub[t] + ub[6 + t] + ub[12 + t];
    __syncthreads();
    int w = t >> 5, lane = t & 31;
    int a = blockIdx.x * 8 + w;                   // < 2048
    float acc[6] = {};
    const float* hx0 = g_hx + 0 * AH + a * Hd;
    const float* hx1 = g_hx + 1 * AH + a * Hd;
    const float* hx2 = g_hx + 2 * AH + a * Hd;
    const float* zb  = g_z + a * Hd;
    for (int c = lane; c < Hd; c += 32) {
        float x0 = hx0[c], x1 = hx1[c], x2 = hx2[c];
        float z0 = zb[0 * AH + c], z1 = zb[1 * AH + c], z2 = zb[2 * AH + c];
        float z3 = zb[3 * AH + c], z4 = zb[4 * AH + c], z5 = zb[5 * AH + c];
        float o0 = z0 * x0 + (1.f - z0) * x1 + z1 * x0 + (1.f - z1) * x2;
        float o1 = z2 * x1 + (1.f - z2) * x0 + z3 * x1 + (1.f - z3) * x2;
        float o2 = z4 * x2 + (1.f - z4) * x0 + z5 * x2 + (1.f - z5) * x1;
#pragma unroll
        for (int tg = 0; tg < 6; tg++)
            acc[tg] += o0 * su[c * 6 + tg]
                     + o1 * su[1200 + c * 6 + tg]
                     + o2 * su[2400 + c * 6 + tg];
    }
#pragma unroll
    for (int o = 16; o; o >>= 1)
#pragma unroll
        for (int tg = 0; tg < 6; tg++)
            acc[tg] += __shfl_xor_sync(0xffffffffu, acc[tg], o);
    if (lane == 0)
#pragma unroll
        for (int tg = 0; tg < 6; tg++)
            out[a * 6 + tg] = acc[tg] + sb[tg];
}

// ---------------- host launcher ----------------
extern "C" void kernel_launch(void* const* d_in, const int* in_sizes, int n_in,
                              void* d_out, int out_size) {
    const float* x_a     = (const float*)d_in[0];
    const float* x_v     = (const float*)d_in[1];
    const float* x_t     = (const float*)d_in[2];
    const float* fc0_w   = (const float*)d_in[3];
    const float* fc0_b   = (const float*)d_in[4];
    const float* conv_w  = (const float*)d_in[5];
    const float* tm_w    = (const float*)d_in[6];
    const float* tm_b    = (const float*)d_in[7];
    const float* cross_w = (const float*)d_in[8];
    const float* cross_b = (const float*)d_in[9];
    const float* uni_w   = (const float*)d_in[10];
    const float* uni_b   = (const float*)d_in[11];
    float* out = (float*)d_out;

    const float beta0 = 0.40546510810816438f;  // log(1.5)
    const float beta1 = 0.22314355131420976f;  // log(1.25)

    prep_kernel<<<256, 256>>>(x_a, x_v, x_t);
    intra_kernel<<<96, 256>>>();

    gemm2<0><<<dim3(1, 96, 1), 128>>>(fc0_w, fc0_b, 0.f);

    adjmul_kernel<<<96, 256>>>();
    gemm2<1><<<dim3(1, 96, 1), 128>>>(conv_w, nullptr, beta0);
    adjmul_kernel<<<96, 256>>>();
    gemm2<1><<<dim3(1, 96, 1), 128>>>(conv_w + 400 * Hd, nullptr, beta1);

    gemm2<2><<<dim3(1, 32, 3), 128>>>(tm_w, tm_b, 0.f);
    gemm2<3><<<dim3(1, 32, 6), 128>>>(cross_w, cross_b, 0.f);

    joint_kernel<<<256, 256>>>(uni_w, uni_b, out);
}